// round 3
// baseline (speedup 1.0000x reference)
#include <cuda_runtime.h>
#include <cuda_bf16.h>
#include <math.h>

// Problem constants
#define B 8
#define N 1024
#define C 768
#define H 12
#define D 64
#define M_ROWS (B * N)          // 8192

// ---------------- scratch (device globals; no allocation allowed) ------------
__device__ float g_q[M_ROWS * C];
__device__ float g_k[M_ROWS * C];
__device__ float g_v[M_ROWS * C];
__device__ float g_att[M_ROWS * C];

// ---------------- generic NT GEMM with bias: Cmat = A @ W^T + bias -----------
// A: [M,K] row-major, W: [Nn,K] row-major, Cmat: [M,Nn]
// 128x64 block tile, BK=16, 256 threads, 8x4 per-thread accumulator.
#define BM 128
#define BN 64
#define BK 16

__global__ __launch_bounds__(256) void gemm_nt_bias(
    const float* __restrict__ A, const float* __restrict__ W,
    const float* __restrict__ bias, float* __restrict__ Cmat,
    int M, int Nn, int K)
{
    __shared__ float As[BK][BM + 4];
    __shared__ float Bs[BK][BN + 4];

    const int tid = threadIdx.x;
    const int tx = tid & 15;           // 16 col-groups * 4 cols = 64
    const int ty = tid >> 4;           // 16 row-groups * 8 rows = 128
    const int m0 = blockIdx.y * BM;
    const int n0 = blockIdx.x * BN;

    const int lr = tid >> 2;           // 0..63
    const int lk = (tid & 3) * 4;      // 0,4,8,12

    float acc[8][4];
#pragma unroll
    for (int i = 0; i < 8; i++)
#pragma unroll
        for (int j = 0; j < 4; j++) acc[i][j] = 0.0f;

    for (int k0 = 0; k0 < K; k0 += BK) {
        // A tile: 128 rows x 16 k  (each thread: rows lr and lr+64)
        float4 a0 = *(const float4*)(A + (size_t)(m0 + lr) * K + k0 + lk);
        float4 a1 = *(const float4*)(A + (size_t)(m0 + lr + 64) * K + k0 + lk);
        // B tile: 64 rows x 16 k
        float4 b  = *(const float4*)(W + (size_t)(n0 + lr) * K + k0 + lk);

        As[lk + 0][lr] = a0.x; As[lk + 1][lr] = a0.y;
        As[lk + 2][lr] = a0.z; As[lk + 3][lr] = a0.w;
        As[lk + 0][lr + 64] = a1.x; As[lk + 1][lr + 64] = a1.y;
        As[lk + 2][lr + 64] = a1.z; As[lk + 3][lr + 64] = a1.w;
        Bs[lk + 0][lr] = b.x; Bs[lk + 1][lr] = b.y;
        Bs[lk + 2][lr] = b.z; Bs[lk + 3][lr] = b.w;
        __syncthreads();

#pragma unroll
        for (int kk = 0; kk < BK; kk++) {
            float4 av0 = *(const float4*)&As[kk][ty * 8];
            float4 av1 = *(const float4*)&As[kk][ty * 8 + 4];
            float4 bv  = *(const float4*)&Bs[kk][tx * 4];
            float ar[8] = {av0.x, av0.y, av0.z, av0.w,
                           av1.x, av1.y, av1.z, av1.w};
            float br[4] = {bv.x, bv.y, bv.z, bv.w};
#pragma unroll
            for (int i = 0; i < 8; i++)
#pragma unroll
                for (int j = 0; j < 4; j++)
                    acc[i][j] = fmaf(ar[i], br[j], acc[i][j]);
        }
        __syncthreads();
    }

    float4 bb = *(const float4*)(bias + n0 + tx * 4);
    float br[4] = {bb.x, bb.y, bb.z, bb.w};
#pragma unroll
    for (int i = 0; i < 8; i++) {
        float4 o;
        o.x = acc[i][0] + br[0];
        o.y = acc[i][1] + br[1];
        o.z = acc[i][2] + br[2];
        o.w = acc[i][3] + br[3];
        *(float4*)(Cmat + (size_t)(m0 + ty * 8 + i) * Nn + n0 + tx * 4) = o;
    }
}

// ---------------- flash attention: per (b,h), 64-query tiles -----------------
// Q/K/V layout: [B*N, C] with head h at column offset h*64.
// Output written to g_att (same layout), scaled by head_mask^2 / l.
#define SM_STRIDE 68

__global__ __launch_bounds__(256) void attn_kernel(
    const float* __restrict__ Q, const float* __restrict__ K,
    const float* __restrict__ V, const float* __restrict__ hm,
    float* __restrict__ O)
{
    extern __shared__ float sm[];
    float (*Qt)[SM_STRIDE] = (float(*)[SM_STRIDE])sm;                 // Qt[dd][row]
    float (*Kt)[SM_STRIDE] = (float(*)[SM_STRIDE])(sm + 64 * SM_STRIDE);
    float (*Vs)[SM_STRIDE] = (float(*)[SM_STRIDE])(sm + 2 * 64 * SM_STRIDE);
    float (*Pt)[SM_STRIDE] = (float(*)[SM_STRIDE])(sm + 3 * 64 * SM_STRIDE);

    const int b = blockIdx.z, h = blockIdx.y;
    const int q0 = blockIdx.x * 64;
    const int tid = threadIdx.x;
    const int tx = tid & 15;
    const int ty = tid >> 4;

    const float scale = 0.125f;  // 64^-0.5

    const int lrow = tid >> 2;          // 0..63
    const int lc0  = (tid & 3) * 16;    // chunk base within 64 dims

    const float* qbase = Q + ((size_t)(b * N + q0)) * C + h * D;
    const float* kbase = K + ((size_t)(b * N)) * C + h * D;
    const float* vbase = V + ((size_t)(b * N)) * C + h * D;

    // Load Q tile transposed, pre-scaled
#pragma unroll
    for (int r = 0; r < 4; r++) {
        int dd = lc0 + r * 4;
        float4 v = *(const float4*)(qbase + (size_t)lrow * C + dd);
        Qt[dd + 0][lrow] = v.x * scale;
        Qt[dd + 1][lrow] = v.y * scale;
        Qt[dd + 2][lrow] = v.z * scale;
        Qt[dd + 3][lrow] = v.w * scale;
    }

    float m_i[4], l_i[4], acc[4][4];
#pragma unroll
    for (int i = 0; i < 4; i++) {
        m_i[i] = -INFINITY;
        l_i[i] = 0.0f;
#pragma unroll
        for (int j = 0; j < 4; j++) acc[i][j] = 0.0f;
    }

    for (int k0 = 0; k0 < N; k0 += 64) {
        __syncthreads();   // protect Kt/Vs/Pt from previous iteration readers
        // load K tile transposed + V tile natural
#pragma unroll
        for (int r = 0; r < 4; r++) {
            int dd = lc0 + r * 4;
            float4 kv = *(const float4*)(kbase + (size_t)(k0 + lrow) * C + dd);
            Kt[dd + 0][lrow] = kv.x;
            Kt[dd + 1][lrow] = kv.y;
            Kt[dd + 2][lrow] = kv.z;
            Kt[dd + 3][lrow] = kv.w;
            float4 vv = *(const float4*)(vbase + (size_t)(k0 + lrow) * C + dd);
            *(float4*)&Vs[lrow][dd] = vv;
        }
        __syncthreads();

        // S = Q K^T  (rows ty*4.., cols tx*4..)
        float s[4][4];
#pragma unroll
        for (int i = 0; i < 4; i++)
#pragma unroll
            for (int j = 0; j < 4; j++) s[i][j] = 0.0f;
#pragma unroll
        for (int kk = 0; kk < 64; kk++) {
            float4 qv = *(const float4*)&Qt[kk][ty * 4];
            float4 kv = *(const float4*)&Kt[kk][tx * 4];
            float qr[4] = {qv.x, qv.y, qv.z, qv.w};
            float kr[4] = {kv.x, kv.y, kv.z, kv.w};
#pragma unroll
            for (int i = 0; i < 4; i++)
#pragma unroll
                for (int j = 0; j < 4; j++)
                    s[i][j] = fmaf(qr[i], kr[j], s[i][j]);
        }

        // online softmax: row stats shared across the 16 lanes of each ty-group
        float mnew[4];
#pragma unroll
        for (int i = 0; i < 4; i++) {
            float rm = fmaxf(fmaxf(s[i][0], s[i][1]), fmaxf(s[i][2], s[i][3]));
#pragma unroll
            for (int off = 8; off > 0; off >>= 1)
                rm = fmaxf(rm, __shfl_xor_sync(0xffffffffu, rm, off));
            mnew[i] = fmaxf(m_i[i], rm);
        }
#pragma unroll
        for (int i = 0; i < 4; i++) {
            float alpha = __expf(m_i[i] - mnew[i]);
            l_i[i] *= alpha;
#pragma unroll
            for (int j = 0; j < 4; j++) acc[i][j] *= alpha;
        }
#pragma unroll
        for (int i = 0; i < 4; i++) {
            float rs = 0.0f;
#pragma unroll
            for (int j = 0; j < 4; j++) {
                float p = __expf(s[i][j] - mnew[i]);
                s[i][j] = p;
                rs += p;
            }
#pragma unroll
            for (int off = 8; off > 0; off >>= 1)
                rs += __shfl_xor_sync(0xffffffffu, rs, off);
            l_i[i] += rs;
            m_i[i] = mnew[i];
        }

        // store P transposed: Pt[key][qrow]
#pragma unroll
        for (int i = 0; i < 4; i++)
#pragma unroll
            for (int j = 0; j < 4; j++)
                Pt[tx * 4 + j][ty * 4 + i] = s[i][j];
        __syncthreads();

        // O += P @ V
#pragma unroll
        for (int kk = 0; kk < 64; kk++) {
            float4 pv = *(const float4*)&Pt[kk][ty * 4];
            float4 vv = *(const float4*)&Vs[kk][tx * 4];
            float pr[4] = {pv.x, pv.y, pv.z, pv.w};
            float vr[4] = {vv.x, vv.y, vv.z, vv.w};
#pragma unroll
            for (int i = 0; i < 4; i++)
#pragma unroll
                for (int j = 0; j < 4; j++)
                    acc[i][j] = fmaf(pr[i], vr[j], acc[i][j]);
        }
    }

    // epilogue: divide by l, apply head_mask^2, write to scratch
    float mk = hm[b * H + h];
    float m2 = mk * mk;
    float* obase = O + ((size_t)(b * N + q0)) * C + h * D;
#pragma unroll
    for (int i = 0; i < 4; i++) {
        float inv = m2 / l_i[i];
        float4 o;
        o.x = acc[i][0] * inv;
        o.y = acc[i][1] * inv;
        o.z = acc[i][2] * inv;
        o.w = acc[i][3] * inv;
        *(float4*)(obase + (size_t)(ty * 4 + i) * C + tx * 4) = o;
    }
}

// ---------------- launch ------------------------------------------------------
extern "C" void kernel_launch(void* const* d_in, const int* in_sizes, int n_in,
                              void* d_out, int out_size)
{
    const float* x   = (const float*)d_in[0];
    const float* hm  = (const float*)d_in[1];
    const float* q_w = (const float*)d_in[2];
    const float* q_b = (const float*)d_in[3];
    const float* k_w = (const float*)d_in[4];
    const float* k_b = (const float*)d_in[5];
    const float* v_w = (const float*)d_in[6];
    const float* v_b = (const float*)d_in[7];
    const float* p_w = (const float*)d_in[8];
    const float* p_b = (const float*)d_in[9];
    float* out = (float*)d_out;

    float *pq, *pk, *pv, *pa;
    cudaGetSymbolAddress((void**)&pq, g_q);
    cudaGetSymbolAddress((void**)&pk, g_k);
    cudaGetSymbolAddress((void**)&pv, g_v);
    cudaGetSymbolAddress((void**)&pa, g_att);

    dim3 gemm_grid(C / BN, M_ROWS / BM);     // (12, 64)
    gemm_nt_bias<<<gemm_grid, 256>>>(x, q_w, q_b, pq, M_ROWS, C, C);
    gemm_nt_bias<<<gemm_grid, 256>>>(x, k_w, k_b, pk, M_ROWS, C, C);
    gemm_nt_bias<<<gemm_grid, 256>>>(x, v_w, v_b, pv, M_ROWS, C, C);

    const int attn_smem = 4 * 64 * SM_STRIDE * (int)sizeof(float);  // 69632 B
    cudaFuncSetAttribute(attn_kernel,
                         cudaFuncAttributeMaxDynamicSharedMemorySize, attn_smem);
    dim3 attn_grid(N / 64, H, B);            // (16, 12, 8)
    attn_kernel<<<attn_grid, 256, attn_smem>>>(pq, pk, pv, hm, pa);

    gemm_nt_bias<<<gemm_grid, 256>>>(pa, p_w, p_b, out, M_ROWS, C, C);
}

// round 8
// speedup vs baseline: 1.2348x; 1.2348x over previous
#include <cuda_runtime.h>
#include <cuda_bf16.h>
#include <mma.h>
#include <math.h>
#include <stdint.h>

using namespace nvcuda;

// Problem constants
#define B 8
#define N 1024
#define C 768
#define H 12
#define D 64
#define M_ROWS (B * N)          // 8192

// ---------------- scratch (device globals; no allocation allowed) ------------
__device__ float g_q[M_ROWS * C];
__device__ float g_k[M_ROWS * C];
__device__ float g_v[M_ROWS * C];
__device__ float g_att[M_ROWS * C];
__device__ float g_bias_rep[16 * C];   // 16 replicated rows of current bias

// ---------------- bias replicate (seeds WMMA accumulator fragments) ----------
__global__ void bias_rep_kernel(const float* __restrict__ bias) {
    int i = blockIdx.x * 256 + threadIdx.x;
    if (i < 16 * C) g_bias_rep[i] = bias[i % C];
}

// ============================================================================
// WMMA bf16-split GEMM: Cmat[M,768] = A[M,768] @ W[768,768]^T + bias
//   x = hi + lo (bf16 each); y ~= hi*hiW + hi*loW + lo*hiW, fp32 accumulate.
// CTA tile 128x128, 8 warps (4m x 2n), warp tile 32x64 (2x4 wmma frags).
// K staged in chunks of 32 f32 -> hi/lo bf16 tiles in smem (ld=40).
// ============================================================================
#define KC 32
#define LDT 40                  // smem leading dim (bf16), multiple of 8

__device__ __forceinline__ void stage_split(
    const float* __restrict__ src, int row0, int k0,
    __nv_bfloat16 (*hi)[LDT], __nv_bfloat16 (*lo)[LDT], int tid)
{
    const int row = tid >> 1;              // 0..127
    const int cbase = (tid & 1) * 16;      // 0 or 16
#pragma unroll
    for (int q = 0; q < 4; q++) {
        int col = cbase + q * 4;
        float4 v = *(const float4*)(src + (size_t)(row0 + row) * C + k0 + col);
        __nv_bfloat16 h0 = __float2bfloat16(v.x);
        __nv_bfloat16 h1 = __float2bfloat16(v.y);
        __nv_bfloat16 h2 = __float2bfloat16(v.z);
        __nv_bfloat16 h3 = __float2bfloat16(v.w);
        hi[row][col + 0] = h0;
        hi[row][col + 1] = h1;
        hi[row][col + 2] = h2;
        hi[row][col + 3] = h3;
        lo[row][col + 0] = __float2bfloat16(v.x - __bfloat162float(h0));
        lo[row][col + 1] = __float2bfloat16(v.y - __bfloat162float(h1));
        lo[row][col + 2] = __float2bfloat16(v.z - __bfloat162float(h2));
        lo[row][col + 3] = __float2bfloat16(v.w - __bfloat162float(h3));
    }
}

__global__ __launch_bounds__(256) void gemm_wmma(
    const float* __restrict__ A, const float* __restrict__ W,
    float* __restrict__ Cmat)
{
    __shared__ __nv_bfloat16 As_hi[128][LDT];
    __shared__ __nv_bfloat16 As_lo[128][LDT];
    __shared__ __nv_bfloat16 Ws_hi[128][LDT];
    __shared__ __nv_bfloat16 Ws_lo[128][LDT];

    const int tid = threadIdx.x;
    const int wid = tid >> 5;
    const int wm = wid >> 1;               // 0..3 (m group of 32 rows)
    const int wn = wid & 1;                // 0..1 (n group of 64 cols)
    const int m0 = blockIdx.y * 128;
    const int n0 = blockIdx.x * 128;

    wmma::fragment<wmma::accumulator, 16, 16, 16, float> acc[2][4];
#pragma unroll
    for (int mi = 0; mi < 2; mi++)
#pragma unroll
        for (int ni = 0; ni < 4; ni++)
            wmma::load_matrix_sync(acc[mi][ni],
                g_bias_rep + n0 + wn * 64 + ni * 16, C, wmma::mem_row_major);

    for (int k0 = 0; k0 < C; k0 += KC) {
        stage_split(A, m0, k0, As_hi, As_lo, tid);
        stage_split(W, n0, k0, Ws_hi, Ws_lo, tid);
        __syncthreads();

#pragma unroll
        for (int ks = 0; ks < 2; ks++) {
            const int kk = ks * 16;
            wmma::fragment<wmma::matrix_a, 16, 16, 16, __nv_bfloat16,
                           wmma::row_major> a_hi[2], a_lo[2];
#pragma unroll
            for (int mi = 0; mi < 2; mi++) {
                wmma::load_matrix_sync(a_hi[mi], &As_hi[wm * 32 + mi * 16][kk], LDT);
                wmma::load_matrix_sync(a_lo[mi], &As_lo[wm * 32 + mi * 16][kk], LDT);
            }
#pragma unroll
            for (int ni = 0; ni < 4; ni++) {
                wmma::fragment<wmma::matrix_b, 16, 16, 16, __nv_bfloat16,
                               wmma::col_major> b_hi, b_lo;
                wmma::load_matrix_sync(b_hi, &Ws_hi[wn * 64 + ni * 16][kk], LDT);
                wmma::load_matrix_sync(b_lo, &Ws_lo[wn * 64 + ni * 16][kk], LDT);
#pragma unroll
                for (int mi = 0; mi < 2; mi++) {
                    wmma::mma_sync(acc[mi][ni], a_hi[mi], b_hi, acc[mi][ni]);
                    wmma::mma_sync(acc[mi][ni], a_hi[mi], b_lo, acc[mi][ni]);
                    wmma::mma_sync(acc[mi][ni], a_lo[mi], b_hi, acc[mi][ni]);
                }
            }
        }
        __syncthreads();
    }

#pragma unroll
    for (int mi = 0; mi < 2; mi++)
#pragma unroll
        for (int ni = 0; ni < 4; ni++)
            wmma::store_matrix_sync(
                Cmat + (size_t)(m0 + wm * 32 + mi * 16) * C + n0 + wn * 64 + ni * 16,
                acc[mi][ni], C, wmma::mem_row_major);
}

// ---------------- flash attention: per (b,h), 64-query tiles (unchanged) -----
#define SM_STRIDE 68

__global__ __launch_bounds__(256) void attn_kernel(
    const float* __restrict__ Q, const float* __restrict__ K,
    const float* __restrict__ V, const float* __restrict__ hm,
    float* __restrict__ O)
{
    extern __shared__ float smf[];
    float (*Qt)[SM_STRIDE] = (float(*)[SM_STRIDE])smf;
    float (*Kt)[SM_STRIDE] = (float(*)[SM_STRIDE])(smf + 64 * SM_STRIDE);
    float (*Vs)[SM_STRIDE] = (float(*)[SM_STRIDE])(smf + 2 * 64 * SM_STRIDE);
    float (*Pt)[SM_STRIDE] = (float(*)[SM_STRIDE])(smf + 3 * 64 * SM_STRIDE);

    const int b = blockIdx.z, h = blockIdx.y;
    const int q0 = blockIdx.x * 64;
    const int tid = threadIdx.x;
    const int tx = tid & 15;
    const int ty = tid >> 4;

    const float scale = 0.125f;

    const int lrow = tid >> 2;
    const int lc0  = (tid & 3) * 16;

    const float* qbase = Q + ((size_t)(b * N + q0)) * C + h * D;
    const float* kbase = K + ((size_t)(b * N)) * C + h * D;
    const float* vbase = V + ((size_t)(b * N)) * C + h * D;

#pragma unroll
    for (int r = 0; r < 4; r++) {
        int dd = lc0 + r * 4;
        float4 v = *(const float4*)(qbase + (size_t)lrow * C + dd);
        Qt[dd + 0][lrow] = v.x * scale;
        Qt[dd + 1][lrow] = v.y * scale;
        Qt[dd + 2][lrow] = v.z * scale;
        Qt[dd + 3][lrow] = v.w * scale;
    }

    float m_i[4], l_i[4], acc[4][4];
#pragma unroll
    for (int i = 0; i < 4; i++) {
        m_i[i] = -INFINITY;
        l_i[i] = 0.0f;
#pragma unroll
        for (int j = 0; j < 4; j++) acc[i][j] = 0.0f;
    }

    for (int k0 = 0; k0 < N; k0 += 64) {
        __syncthreads();
#pragma unroll
        for (int r = 0; r < 4; r++) {
            int dd = lc0 + r * 4;
            float4 kv = *(const float4*)(kbase + (size_t)(k0 + lrow) * C + dd);
            Kt[dd + 0][lrow] = kv.x;
            Kt[dd + 1][lrow] = kv.y;
            Kt[dd + 2][lrow] = kv.z;
            Kt[dd + 3][lrow] = kv.w;
            float4 vv = *(const float4*)(vbase + (size_t)(k0 + lrow) * C + dd);
            *(float4*)&Vs[lrow][dd] = vv;
        }
        __syncthreads();

        float s[4][4];
#pragma unroll
        for (int i = 0; i < 4; i++)
#pragma unroll
            for (int j = 0; j < 4; j++) s[i][j] = 0.0f;
#pragma unroll
        for (int kk = 0; kk < 64; kk++) {
            float4 qv = *(const float4*)&Qt[kk][ty * 4];
            float4 kv = *(const float4*)&Kt[kk][tx * 4];
            float qr[4] = {qv.x, qv.y, qv.z, qv.w};
            float kr[4] = {kv.x, kv.y, kv.z, kv.w};
#pragma unroll
            for (int i = 0; i < 4; i++)
#pragma unroll
                for (int j = 0; j < 4; j++)
                    s[i][j] = fmaf(qr[i], kr[j], s[i][j]);
        }

        float mnew[4];
#pragma unroll
        for (int i = 0; i < 4; i++) {
            float rm = fmaxf(fmaxf(s[i][0], s[i][1]), fmaxf(s[i][2], s[i][3]));
#pragma unroll
            for (int off = 8; off > 0; off >>= 1)
                rm = fmaxf(rm, __shfl_xor_sync(0xffffffffu, rm, off));
            mnew[i] = fmaxf(m_i[i], rm);
        }
#pragma unroll
        for (int i = 0; i < 4; i++) {
            float alpha = __expf(m_i[i] - mnew[i]);
            l_i[i] *= alpha;
#pragma unroll
            for (int j = 0; j < 4; j++) acc[i][j] *= alpha;
        }
#pragma unroll
        for (int i = 0; i < 4; i++) {
            float rs = 0.0f;
#pragma unroll
            for (int j = 0; j < 4; j++) {
                float p = __expf(s[i][j] - mnew[i]);
                s[i][j] = p;
                rs += p;
            }
#pragma unroll
            for (int off = 8; off > 0; off >>= 1)
                rs += __shfl_xor_sync(0xffffffffu, rs, off);
            l_i[i] += rs;
            m_i[i] = mnew[i];
        }

#pragma unroll
        for (int i = 0; i < 4; i++)
#pragma unroll
            for (int j = 0; j < 4; j++)
                Pt[tx * 4 + j][ty * 4 + i] = s[i][j];
        __syncthreads();

#pragma unroll
        for (int kk = 0; kk < 64; kk++) {
            float4 pv = *(const float4*)&Pt[kk][ty * 4];
            float4 vv = *(const float4*)&Vs[kk][tx * 4];
            float pr[4] = {pv.x, pv.y, pv.z, pv.w};
            float vr[4] = {vv.x, vv.y, vv.z, vv.w};
#pragma unroll
            for (int i = 0; i < 4; i++)
#pragma unroll
                for (int j = 0; j < 4; j++)
                    acc[i][j] = fmaf(pr[i], vr[j], acc[i][j]);
        }
    }

    float mk = hm[b * H + h];
    float m2 = mk * mk;
    float* obase = O + ((size_t)(b * N + q0)) * C + h * D;
#pragma unroll
    for (int i = 0; i < 4; i++) {
        float inv = m2 / l_i[i];
        float4 o;
        o.x = acc[i][0] * inv;
        o.y = acc[i][1] * inv;
        o.z = acc[i][2] * inv;
        o.w = acc[i][3] * inv;
        *(float4*)(obase + (size_t)(ty * 4 + i) * C + tx * 4) = o;
    }
}

// ---------------- launch ------------------------------------------------------
extern "C" void kernel_launch(void* const* d_in, const int* in_sizes, int n_in,
                              void* d_out, int out_size)
{
    const float* x   = (const float*)d_in[0];
    const float* hm  = (const float*)d_in[1];
    const float* q_w = (const float*)d_in[2];
    const float* q_b = (const float*)d_in[3];
    const float* k_w = (const float*)d_in[4];
    const float* k_b = (const float*)d_in[5];
    const float* v_w = (const float*)d_in[6];
    const float* v_b = (const float*)d_in[7];
    const float* p_w = (const float*)d_in[8];
    const float* p_b = (const float*)d_in[9];
    float* out = (float*)d_out;

    float *pq, *pk, *pv, *pa;
    cudaGetSymbolAddress((void**)&pq, g_q);
    cudaGetSymbolAddress((void**)&pk, g_k);
    cudaGetSymbolAddress((void**)&pv, g_v);
    cudaGetSymbolAddress((void**)&pa, g_att);

    dim3 ggrid(C / 128, M_ROWS / 128);       // (6, 64)
    bias_rep_kernel<<<48, 256>>>(q_b);
    gemm_wmma<<<ggrid, 256>>>(x, q_w, pq);
    bias_rep_kernel<<<48, 256>>>(k_b);
    gemm_wmma<<<ggrid, 256>>>(x, k_w, pk);
    bias_rep_kernel<<<48, 256>>>(v_b);
    gemm_wmma<<<ggrid, 256>>>(x, v_w, pv);

    const int attn_smem = 4 * 64 * SM_STRIDE * (int)sizeof(float);  // 69632 B
    cudaFuncSetAttribute(attn_kernel,
                         cudaFuncAttributeMaxDynamicSharedMemorySize, attn_smem);
    dim3 attn_grid(N / 64, H, B);            // (16, 12, 8)
    attn_kernel<<<attn_grid, 256, attn_smem>>>(pq, pk, pv, hm, pa);

    bias_rep_kernel<<<48, 256>>>(p_b);
    gemm_wmma<<<ggrid, 256>>>(pa, p_w, out);
}

// round 9
// speedup vs baseline: 1.6415x; 1.3293x over previous
#include <cuda_runtime.h>
#include <cuda_bf16.h>
#include <cuda_fp16.h>
#include <mma.h>
#include <math.h>
#include <stdint.h>

using namespace nvcuda;

// Problem constants
#define B 8
#define N 1024
#define C 768
#define H 12
#define D 64
#define M_ROWS (B * N)          // 8192

// ---------------- scratch (device globals; no allocation allowed) ------------
__device__ float g_q[M_ROWS * C];
__device__ float g_k[M_ROWS * C];
__device__ float g_v[M_ROWS * C];
__device__ float g_att[M_ROWS * C];
__device__ float g_bias_rep[16 * C];   // 16 replicated rows of current bias

// ---------------- bias replicate (seeds WMMA accumulator fragments) ----------
__global__ void bias_rep_kernel(const float* __restrict__ bias) {
    int i = blockIdx.x * 256 + threadIdx.x;
    if (i < 16 * C) g_bias_rep[i] = bias[i % C];
}

// ============================================================================
// WMMA bf16-split GEMM (unchanged from R8; measured 185us each)
// ============================================================================
#define KC 32
#define LDT 40

__device__ __forceinline__ void stage_split(
    const float* __restrict__ src, int row0, int k0,
    __nv_bfloat16 (*hi)[LDT], __nv_bfloat16 (*lo)[LDT], int tid)
{
    const int row = tid >> 1;
    const int cbase = (tid & 1) * 16;
#pragma unroll
    for (int q = 0; q < 4; q++) {
        int col = cbase + q * 4;
        float4 v = *(const float4*)(src + (size_t)(row0 + row) * C + k0 + col);
        __nv_bfloat16 h0 = __float2bfloat16(v.x);
        __nv_bfloat16 h1 = __float2bfloat16(v.y);
        __nv_bfloat16 h2 = __float2bfloat16(v.z);
        __nv_bfloat16 h3 = __float2bfloat16(v.w);
        hi[row][col + 0] = h0;
        hi[row][col + 1] = h1;
        hi[row][col + 2] = h2;
        hi[row][col + 3] = h3;
        lo[row][col + 0] = __float2bfloat16(v.x - __bfloat162float(h0));
        lo[row][col + 1] = __float2bfloat16(v.y - __bfloat162float(h1));
        lo[row][col + 2] = __float2bfloat16(v.z - __bfloat162float(h2));
        lo[row][col + 3] = __float2bfloat16(v.w - __bfloat162float(h3));
    }
}

__global__ __launch_bounds__(256) void gemm_wmma(
    const float* __restrict__ A, const float* __restrict__ W,
    float* __restrict__ Cmat)
{
    __shared__ __nv_bfloat16 As_hi[128][LDT];
    __shared__ __nv_bfloat16 As_lo[128][LDT];
    __shared__ __nv_bfloat16 Ws_hi[128][LDT];
    __shared__ __nv_bfloat16 Ws_lo[128][LDT];

    const int tid = threadIdx.x;
    const int wid = tid >> 5;
    const int wm = wid >> 1;
    const int wn = wid & 1;
    const int m0 = blockIdx.y * 128;
    const int n0 = blockIdx.x * 128;

    wmma::fragment<wmma::accumulator, 16, 16, 16, float> acc[2][4];
#pragma unroll
    for (int mi = 0; mi < 2; mi++)
#pragma unroll
        for (int ni = 0; ni < 4; ni++)
            wmma::load_matrix_sync(acc[mi][ni],
                g_bias_rep + n0 + wn * 64 + ni * 16, C, wmma::mem_row_major);

    for (int k0 = 0; k0 < C; k0 += KC) {
        stage_split(A, m0, k0, As_hi, As_lo, tid);
        stage_split(W, n0, k0, Ws_hi, Ws_lo, tid);
        __syncthreads();

#pragma unroll
        for (int ks = 0; ks < 2; ks++) {
            const int kk = ks * 16;
            wmma::fragment<wmma::matrix_a, 16, 16, 16, __nv_bfloat16,
                           wmma::row_major> a_hi[2], a_lo[2];
#pragma unroll
            for (int mi = 0; mi < 2; mi++) {
                wmma::load_matrix_sync(a_hi[mi], &As_hi[wm * 32 + mi * 16][kk], LDT);
                wmma::load_matrix_sync(a_lo[mi], &As_lo[wm * 32 + mi * 16][kk], LDT);
            }
#pragma unroll
            for (int ni = 0; ni < 4; ni++) {
                wmma::fragment<wmma::matrix_b, 16, 16, 16, __nv_bfloat16,
                               wmma::col_major> b_hi, b_lo;
                wmma::load_matrix_sync(b_hi, &Ws_hi[wn * 64 + ni * 16][kk], LDT);
                wmma::load_matrix_sync(b_lo, &Ws_lo[wn * 64 + ni * 16][kk], LDT);
#pragma unroll
                for (int mi = 0; mi < 2; mi++) {
                    wmma::mma_sync(acc[mi][ni], a_hi[mi], b_hi, acc[mi][ni]);
                    wmma::mma_sync(acc[mi][ni], a_hi[mi], b_lo, acc[mi][ni]);
                    wmma::mma_sync(acc[mi][ni], a_lo[mi], b_hi, acc[mi][ni]);
                }
            }
        }
        __syncthreads();
    }

#pragma unroll
    for (int mi = 0; mi < 2; mi++)
#pragma unroll
        for (int ni = 0; ni < 4; ni++)
            wmma::store_matrix_sync(
                Cmat + (size_t)(m0 + wm * 32 + mi * 16) * C + n0 + wn * 64 + ni * 16,
                acc[mi][ni], C, wmma::mem_row_major);
}

// ============================================================================
// WMMA flash attention (fp16 split): per (b,h), 64-query tiles, 64-key blocks
// ============================================================================
#define AT_LDH 72               // half leading dim (mult of 8)
#define AT_LDF 68               // f32 leading dim (mult of 4)
// smem byte offsets (each half tile 64*72*2 = 9216 B)
#define OFF_QHI 0
#define OFF_QLO 9216
#define OFF_KHI 18432
#define OFF_KLO 27648
#define OFF_VHI 36864
#define OFF_VLO 46080
#define OFF_PHI 55296
#define OFF_PLO 64512
#define OFF_S   73728           // 64*68*4 = 17408
#define OFF_O   91136           // 17408
#define OFF_M   108544          // 256
#define OFF_L   108800          // 256
#define ATTN_SMEM 109056

// stage a [64 x 64] f32 block (row stride C) into hi/lo fp16 tiles (ld AT_LDH)
__device__ __forceinline__ void stage64(
    const float* __restrict__ src_base, __half* hi, __half* lo,
    int tid, float scl)
{
    const int row = tid >> 2;
    const int c0 = (tid & 3) * 16;
    const float* src = src_base + (size_t)row * C + c0;
    __half* ph = hi + row * AT_LDH + c0;
    __half* pl = lo + row * AT_LDH + c0;
#pragma unroll
    for (int i = 0; i < 16; i += 4) {
        float4 v = *(const float4*)(src + i);
        float f0 = v.x * scl, f1 = v.y * scl, f2 = v.z * scl, f3 = v.w * scl;
        __half h0 = __float2half(f0), h1 = __float2half(f1);
        __half h2 = __float2half(f2), h3 = __float2half(f3);
        ph[i + 0] = h0; ph[i + 1] = h1; ph[i + 2] = h2; ph[i + 3] = h3;
        pl[i + 0] = __float2half(f0 - __half2float(h0));
        pl[i + 1] = __float2half(f1 - __half2float(h1));
        pl[i + 2] = __float2half(f2 - __half2float(h2));
        pl[i + 3] = __float2half(f3 - __half2float(h3));
    }
}

__global__ __launch_bounds__(256, 2) void attn_wmma(
    const float* __restrict__ Q, const float* __restrict__ K,
    const float* __restrict__ V, const float* __restrict__ hm,
    float* __restrict__ O)
{
    extern __shared__ char smc[];
    __half* q_hi = (__half*)(smc + OFF_QHI);
    __half* q_lo = (__half*)(smc + OFF_QLO);
    __half* k_hi = (__half*)(smc + OFF_KHI);
    __half* k_lo = (__half*)(smc + OFF_KLO);
    __half* v_hi = (__half*)(smc + OFF_VHI);
    __half* v_lo = (__half*)(smc + OFF_VLO);
    __half* p_hi = (__half*)(smc + OFF_PHI);
    __half* p_lo = (__half*)(smc + OFF_PLO);
    float*  Ss   = (float*)(smc + OFF_S);
    float*  Os   = (float*)(smc + OFF_O);
    float*  sm_m = (float*)(smc + OFF_M);
    float*  sm_l = (float*)(smc + OFF_L);

    const int b = blockIdx.z, h = blockIdx.y;
    const int q0 = blockIdx.x * 64;
    const int tid = threadIdx.x;
    const int wid = tid >> 5;
    const int wm = wid >> 1;               // 0..3: 16-row group
    const int wn = wid & 1;                // 0..1: 32-col group (2 frags)

    // init: stage Q (pre-scaled), zero O, init stats
    stage64(Q + (size_t)(b * N + q0) * C + h * D, q_hi, q_lo, tid, 0.125f);
    for (int i = tid; i < 64 * AT_LDF; i += 256) Os[i] = 0.0f;
    if (tid < 64) { sm_m[tid] = -INFINITY; sm_l[tid] = 0.0f; }
    __syncthreads();

    const float* kbase = K + (size_t)(b * N) * C + h * D;
    const float* vbase = V + (size_t)(b * N) * C + h * D;

    for (int it = 0; it < 16; it++) {
        // stage K/V block
        stage64(kbase + (size_t)(it * 64) * C, k_hi, k_lo, tid, 1.0f);
        stage64(vbase + (size_t)(it * 64) * C, v_hi, v_lo, tid, 1.0f);
        __syncthreads();

        // --- S = Q @ K^T (fp16 split, fp32 acc) ---
        {
            wmma::fragment<wmma::accumulator, 16, 16, 16, float> sacc[2];
            wmma::fill_fragment(sacc[0], 0.0f);
            wmma::fill_fragment(sacc[1], 0.0f);
#pragma unroll
            for (int kk = 0; kk < 64; kk += 16) {
                wmma::fragment<wmma::matrix_a, 16, 16, 16, __half,
                               wmma::row_major> a_hi, a_lo;
                wmma::load_matrix_sync(a_hi, q_hi + wm * 16 * AT_LDH + kk, AT_LDH);
                wmma::load_matrix_sync(a_lo, q_lo + wm * 16 * AT_LDH + kk, AT_LDH);
#pragma unroll
                for (int f = 0; f < 2; f++) {
                    int j0 = wn * 32 + f * 16;
                    wmma::fragment<wmma::matrix_b, 16, 16, 16, __half,
                                   wmma::col_major> b_hi, b_lo;
                    wmma::load_matrix_sync(b_hi, k_hi + j0 * AT_LDH + kk, AT_LDH);
                    wmma::load_matrix_sync(b_lo, k_lo + j0 * AT_LDH + kk, AT_LDH);
                    wmma::mma_sync(sacc[f], a_hi, b_hi, sacc[f]);
                    wmma::mma_sync(sacc[f], a_hi, b_lo, sacc[f]);
                    wmma::mma_sync(sacc[f], a_lo, b_hi, sacc[f]);
                }
            }
#pragma unroll
            for (int f = 0; f < 2; f++)
                wmma::store_matrix_sync(
                    Ss + wm * 16 * AT_LDF + wn * 32 + f * 16, sacc[f],
                    AT_LDF, wmma::mem_row_major);
        }
        __syncthreads();

        // --- online softmax (fp32, per-row quads) ---
        {
            const int row = tid >> 2;
            const int c0 = (tid & 3) * 16;
            float sv[16];
            const float* srow = Ss + row * AT_LDF + c0;
#pragma unroll
            for (int i = 0; i < 16; i++) sv[i] = srow[i];
            float mx = sv[0];
#pragma unroll
            for (int i = 1; i < 16; i++) mx = fmaxf(mx, sv[i]);
            mx = fmaxf(mx, __shfl_xor_sync(0xffffffffu, mx, 1));
            mx = fmaxf(mx, __shfl_xor_sync(0xffffffffu, mx, 2));
            float m_old = sm_m[row];
            float m_new = fmaxf(m_old, mx);
            float alpha = __expf(m_old - m_new);
            float ssum = 0.0f;
#pragma unroll
            for (int i = 0; i < 16; i++) {
                float p = __expf(sv[i] - m_new);
                sv[i] = p;
                ssum += p;
            }
            ssum += __shfl_xor_sync(0xffffffffu, ssum, 1);
            ssum += __shfl_xor_sync(0xffffffffu, ssum, 2);
            if ((tid & 3) == 0) {
                sm_m[row] = m_new;
                sm_l[row] = sm_l[row] * alpha + ssum;
            }
            // write P split
            __half* ph = p_hi + row * AT_LDH + c0;
            __half* pl = p_lo + row * AT_LDH + c0;
#pragma unroll
            for (int i = 0; i < 16; i++) {
                __half hh = __float2half(sv[i]);
                ph[i] = hh;
                pl[i] = __float2half(sv[i] - __half2float(hh));
            }
            // rescale O
            float* orow = Os + row * AT_LDF + c0;
#pragma unroll
            for (int i = 0; i < 16; i++) orow[i] *= alpha;
        }
        __syncthreads();

        // --- O += P @ V (fp16 split) ---
        {
            wmma::fragment<wmma::accumulator, 16, 16, 16, float> oacc[2];
#pragma unroll
            for (int f = 0; f < 2; f++)
                wmma::load_matrix_sync(oacc[f],
                    Os + wm * 16 * AT_LDF + wn * 32 + f * 16, AT_LDF,
                    wmma::mem_row_major);
#pragma unroll
            for (int kk = 0; kk < 64; kk += 16) {
                wmma::fragment<wmma::matrix_a, 16, 16, 16, __half,
                               wmma::row_major> a_hi, a_lo;
                wmma::load_matrix_sync(a_hi, p_hi + wm * 16 * AT_LDH + kk, AT_LDH);
                wmma::load_matrix_sync(a_lo, p_lo + wm * 16 * AT_LDH + kk, AT_LDH);
#pragma unroll
                for (int f = 0; f < 2; f++) {
                    int j0 = wn * 32 + f * 16;
                    wmma::fragment<wmma::matrix_b, 16, 16, 16, __half,
                                   wmma::row_major> b_hi, b_lo;
                    wmma::load_matrix_sync(b_hi, v_hi + kk * AT_LDH + j0, AT_LDH);
                    wmma::load_matrix_sync(b_lo, v_lo + kk * AT_LDH + j0, AT_LDH);
                    wmma::mma_sync(oacc[f], a_hi, b_hi, oacc[f]);
                    wmma::mma_sync(oacc[f], a_hi, b_lo, oacc[f]);
                    wmma::mma_sync(oacc[f], a_lo, b_hi, oacc[f]);
                }
            }
#pragma unroll
            for (int f = 0; f < 2; f++)
                wmma::store_matrix_sync(
                    Os + wm * 16 * AT_LDF + wn * 32 + f * 16, oacc[f],
                    AT_LDF, wmma::mem_row_major);
        }
        __syncthreads();
    }

    // epilogue: O / l * head_mask^2
    {
        float mk = hm[b * H + h];
        float m2 = mk * mk;
        const int row = tid >> 2;
        const int c0 = (tid & 3) * 16;
        float inv = m2 / sm_l[row];
        float* dst = O + (size_t)(b * N + q0 + row) * C + h * D + c0;
        const float* orow = Os + row * AT_LDF + c0;
#pragma unroll
        for (int i = 0; i < 16; i += 4) {
            float4 o;
            o.x = orow[i + 0] * inv;
            o.y = orow[i + 1] * inv;
            o.z = orow[i + 2] * inv;
            o.w = orow[i + 3] * inv;
            *(float4*)(dst + i) = o;
        }
    }
}

// ---------------- launch ------------------------------------------------------
extern "C" void kernel_launch(void* const* d_in, const int* in_sizes, int n_in,
                              void* d_out, int out_size)
{
    const float* x   = (const float*)d_in[0];
    const float* hm  = (const float*)d_in[1];
    const float* q_w = (const float*)d_in[2];
    const float* q_b = (const float*)d_in[3];
    const float* k_w = (const float*)d_in[4];
    const float* k_b = (const float*)d_in[5];
    const float* v_w = (const float*)d_in[6];
    const float* v_b = (const float*)d_in[7];
    const float* p_w = (const float*)d_in[8];
    const float* p_b = (const float*)d_in[9];
    float* out = (float*)d_out;

    float *pq, *pk, *pv, *pa;
    cudaGetSymbolAddress((void**)&pq, g_q);
    cudaGetSymbolAddress((void**)&pk, g_k);
    cudaGetSymbolAddress((void**)&pv, g_v);
    cudaGetSymbolAddress((void**)&pa, g_att);

    dim3 ggrid(C / 128, M_ROWS / 128);       // (6, 64)
    bias_rep_kernel<<<48, 256>>>(q_b);
    gemm_wmma<<<ggrid, 256>>>(x, q_w, pq);
    bias_rep_kernel<<<48, 256>>>(k_b);
    gemm_wmma<<<ggrid, 256>>>(x, k_w, pk);
    bias_rep_kernel<<<48, 256>>>(v_b);
    gemm_wmma<<<ggrid, 256>>>(x, v_w, pv);

    cudaFuncSetAttribute(attn_wmma,
                         cudaFuncAttributeMaxDynamicSharedMemorySize, ATTN_SMEM);
    dim3 attn_grid(N / 64, H, B);            // (16, 12, 8)
    attn_wmma<<<attn_grid, 256, ATTN_SMEM>>>(pq, pk, pv, hm, pa);

    bias_rep_kernel<<<48, 256>>>(p_b);
    gemm_wmma<<<ggrid, 256>>>(pa, p_w, out);
}

// round 10
// speedup vs baseline: 1.9466x; 1.1859x over previous
#include <cuda_runtime.h>
#include <cuda_bf16.h>
#include <cuda_fp16.h>
#include <mma.h>
#include <math.h>
#include <stdint.h>

using namespace nvcuda;

// Problem constants
#define B 8
#define N 1024
#define C 768
#define H 12
#define D 64
#define M_ROWS (B * N)          // 8192

// ---------------- scratch (device globals; no allocation allowed) ------------
__device__ float g_q[M_ROWS * C];
__device__ float g_k[M_ROWS * C];
__device__ float g_v[M_ROWS * C];
__device__ float g_att[M_ROWS * C];
__device__ float g_bias_rep[3 * 16 * C];   // 3 slots of 16 replicated bias rows

// ---------------- bias replicate (3 slots at once) ---------------------------
__global__ void bias_rep3_kernel(const float* __restrict__ b0,
                                 const float* __restrict__ b1,
                                 const float* __restrict__ b2) {
    int i = blockIdx.x * 256 + threadIdx.x;
    if (i < 16 * C) {
        float v0 = b0[i % C];
        float v1 = b1 ? b1[i % C] : 0.0f;
        float v2 = b2 ? b2[i % C] : 0.0f;
        g_bias_rep[i] = v0;
        g_bias_rep[16 * C + i] = v1;
        g_bias_rep[32 * C + i] = v2;
    }
}

// ============================================================================
// WMMA bf16-split GEMM, batched over gridDim.z (selects W / bias slot / dst)
// ============================================================================
#define KC 32
#define LDT 40

__device__ __forceinline__ void stage_split(
    const float* __restrict__ src, int row0, int k0,
    __nv_bfloat16 (*hi)[LDT], __nv_bfloat16 (*lo)[LDT], int tid)
{
    const int row = tid >> 1;
    const int cbase = (tid & 1) * 16;
#pragma unroll
    for (int q = 0; q < 4; q++) {
        int col = cbase + q * 4;
        float4 v = *(const float4*)(src + (size_t)(row0 + row) * C + k0 + col);
        __nv_bfloat16 h0 = __float2bfloat16(v.x);
        __nv_bfloat16 h1 = __float2bfloat16(v.y);
        __nv_bfloat16 h2 = __float2bfloat16(v.z);
        __nv_bfloat16 h3 = __float2bfloat16(v.w);
        hi[row][col + 0] = h0;
        hi[row][col + 1] = h1;
        hi[row][col + 2] = h2;
        hi[row][col + 3] = h3;
        lo[row][col + 0] = __float2bfloat16(v.x - __bfloat162float(h0));
        lo[row][col + 1] = __float2bfloat16(v.y - __bfloat162float(h1));
        lo[row][col + 2] = __float2bfloat16(v.z - __bfloat162float(h2));
        lo[row][col + 3] = __float2bfloat16(v.w - __bfloat162float(h3));
    }
}

__global__ __launch_bounds__(256, 2) void gemm_wmma(
    const float* __restrict__ A,
    const float* __restrict__ W0, const float* __restrict__ W1,
    const float* __restrict__ W2,
    float* __restrict__ D0, float* __restrict__ D1, float* __restrict__ D2)
{
    __shared__ __nv_bfloat16 As_hi[128][LDT];
    __shared__ __nv_bfloat16 As_lo[128][LDT];
    __shared__ __nv_bfloat16 Ws_hi[128][LDT];
    __shared__ __nv_bfloat16 Ws_lo[128][LDT];

    const int tid = threadIdx.x;
    const int wid = tid >> 5;
    const int wm = wid >> 1;
    const int wn = wid & 1;
    const int m0 = blockIdx.y * 128;
    const int n0 = blockIdx.x * 128;
    const int z = blockIdx.z;

    const float* W = (z == 0) ? W0 : (z == 1) ? W1 : W2;
    float* Cmat    = (z == 0) ? D0 : (z == 1) ? D1 : D2;
    const float* brow = g_bias_rep + (size_t)z * 16 * C;

    wmma::fragment<wmma::accumulator, 16, 16, 16, float> acc[2][4];
#pragma unroll
    for (int mi = 0; mi < 2; mi++)
#pragma unroll
        for (int ni = 0; ni < 4; ni++)
            wmma::load_matrix_sync(acc[mi][ni],
                brow + n0 + wn * 64 + ni * 16, C, wmma::mem_row_major);

    for (int k0 = 0; k0 < C; k0 += KC) {
        stage_split(A, m0, k0, As_hi, As_lo, tid);
        stage_split(W, n0, k0, Ws_hi, Ws_lo, tid);
        __syncthreads();

#pragma unroll
        for (int ks = 0; ks < 2; ks++) {
            const int kk = ks * 16;
            wmma::fragment<wmma::matrix_a, 16, 16, 16, __nv_bfloat16,
                           wmma::row_major> a_hi[2], a_lo[2];
#pragma unroll
            for (int mi = 0; mi < 2; mi++) {
                wmma::load_matrix_sync(a_hi[mi], &As_hi[wm * 32 + mi * 16][kk], LDT);
                wmma::load_matrix_sync(a_lo[mi], &As_lo[wm * 32 + mi * 16][kk], LDT);
            }
#pragma unroll
            for (int ni = 0; ni < 4; ni++) {
                wmma::fragment<wmma::matrix_b, 16, 16, 16, __nv_bfloat16,
                               wmma::col_major> b_hi, b_lo;
                wmma::load_matrix_sync(b_hi, &Ws_hi[wn * 64 + ni * 16][kk], LDT);
                wmma::load_matrix_sync(b_lo, &Ws_lo[wn * 64 + ni * 16][kk], LDT);
#pragma unroll
                for (int mi = 0; mi < 2; mi++) {
                    wmma::mma_sync(acc[mi][ni], a_hi[mi], b_hi, acc[mi][ni]);
                    wmma::mma_sync(acc[mi][ni], a_hi[mi], b_lo, acc[mi][ni]);
                    wmma::mma_sync(acc[mi][ni], a_lo[mi], b_hi, acc[mi][ni]);
                }
            }
        }
        __syncthreads();
    }

#pragma unroll
    for (int mi = 0; mi < 2; mi++)
#pragma unroll
        for (int ni = 0; ni < 4; ni++)
            wmma::store_matrix_sync(
                Cmat + (size_t)(m0 + wm * 32 + mi * 16) * C + n0 + wn * 64 + ni * 16,
                acc[mi][ni], C, wmma::mem_row_major);
}

// ============================================================================
// WMMA flash attention (fp16 split) — unchanged from R9 (measured ~430us)
// ============================================================================
#define AT_LDH 72
#define AT_LDF 68
#define OFF_QHI 0
#define OFF_QLO 9216
#define OFF_KHI 18432
#define OFF_KLO 27648
#define OFF_VHI 36864
#define OFF_VLO 46080
#define OFF_PHI 55296
#define OFF_PLO 64512
#define OFF_S   73728
#define OFF_O   91136
#define OFF_M   108544
#define OFF_L   108800
#define ATTN_SMEM 109056

__device__ __forceinline__ void stage64(
    const float* __restrict__ src_base, __half* hi, __half* lo,
    int tid, float scl)
{
    const int row = tid >> 2;
    const int c0 = (tid & 3) * 16;
    const float* src = src_base + (size_t)row * C + c0;
    __half* ph = hi + row * AT_LDH + c0;
    __half* pl = lo + row * AT_LDH + c0;
#pragma unroll
    for (int i = 0; i < 16; i += 4) {
        float4 v = *(const float4*)(src + i);
        float f0 = v.x * scl, f1 = v.y * scl, f2 = v.z * scl, f3 = v.w * scl;
        __half h0 = __float2half(f0), h1 = __float2half(f1);
        __half h2 = __float2half(f2), h3 = __float2half(f3);
        ph[i + 0] = h0; ph[i + 1] = h1; ph[i + 2] = h2; ph[i + 3] = h3;
        pl[i + 0] = __float2half(f0 - __half2float(h0));
        pl[i + 1] = __float2half(f1 - __half2float(h1));
        pl[i + 2] = __float2half(f2 - __half2float(h2));
        pl[i + 3] = __float2half(f3 - __half2float(h3));
    }
}

__global__ __launch_bounds__(256, 2) void attn_wmma(
    const float* __restrict__ Q, const float* __restrict__ K,
    const float* __restrict__ V, const float* __restrict__ hm,
    float* __restrict__ O)
{
    extern __shared__ char smc[];
    __half* q_hi = (__half*)(smc + OFF_QHI);
    __half* q_lo = (__half*)(smc + OFF_QLO);
    __half* k_hi = (__half*)(smc + OFF_KHI);
    __half* k_lo = (__half*)(smc + OFF_KLO);
    __half* v_hi = (__half*)(smc + OFF_VHI);
    __half* v_lo = (__half*)(smc + OFF_VLO);
    __half* p_hi = (__half*)(smc + OFF_PHI);
    __half* p_lo = (__half*)(smc + OFF_PLO);
    float*  Ss   = (float*)(smc + OFF_S);
    float*  Os   = (float*)(smc + OFF_O);
    float*  sm_m = (float*)(smc + OFF_M);
    float*  sm_l = (float*)(smc + OFF_L);

    const int b = blockIdx.z, h = blockIdx.y;
    const int q0 = blockIdx.x * 64;
    const int tid = threadIdx.x;
    const int wid = tid >> 5;
    const int wm = wid >> 1;
    const int wn = wid & 1;

    stage64(Q + (size_t)(b * N + q0) * C + h * D, q_hi, q_lo, tid, 0.125f);
    for (int i = tid; i < 64 * AT_LDF; i += 256) Os[i] = 0.0f;
    if (tid < 64) { sm_m[tid] = -INFINITY; sm_l[tid] = 0.0f; }
    __syncthreads();

    const float* kbase = K + (size_t)(b * N) * C + h * D;
    const float* vbase = V + (size_t)(b * N) * C + h * D;

    for (int it = 0; it < 16; it++) {
        stage64(kbase + (size_t)(it * 64) * C, k_hi, k_lo, tid, 1.0f);
        stage64(vbase + (size_t)(it * 64) * C, v_hi, v_lo, tid, 1.0f);
        __syncthreads();

        {
            wmma::fragment<wmma::accumulator, 16, 16, 16, float> sacc[2];
            wmma::fill_fragment(sacc[0], 0.0f);
            wmma::fill_fragment(sacc[1], 0.0f);
#pragma unroll
            for (int kk = 0; kk < 64; kk += 16) {
                wmma::fragment<wmma::matrix_a, 16, 16, 16, __half,
                               wmma::row_major> a_hi, a_lo;
                wmma::load_matrix_sync(a_hi, q_hi + wm * 16 * AT_LDH + kk, AT_LDH);
                wmma::load_matrix_sync(a_lo, q_lo + wm * 16 * AT_LDH + kk, AT_LDH);
#pragma unroll
                for (int f = 0; f < 2; f++) {
                    int j0 = wn * 32 + f * 16;
                    wmma::fragment<wmma::matrix_b, 16, 16, 16, __half,
                                   wmma::col_major> b_hi, b_lo;
                    wmma::load_matrix_sync(b_hi, k_hi + j0 * AT_LDH + kk, AT_LDH);
                    wmma::load_matrix_sync(b_lo, k_lo + j0 * AT_LDH + kk, AT_LDH);
                    wmma::mma_sync(sacc[f], a_hi, b_hi, sacc[f]);
                    wmma::mma_sync(sacc[f], a_hi, b_lo, sacc[f]);
                    wmma::mma_sync(sacc[f], a_lo, b_hi, sacc[f]);
                }
            }
#pragma unroll
            for (int f = 0; f < 2; f++)
                wmma::store_matrix_sync(
                    Ss + wm * 16 * AT_LDF + wn * 32 + f * 16, sacc[f],
                    AT_LDF, wmma::mem_row_major);
        }
        __syncthreads();

        {
            const int row = tid >> 2;
            const int c0 = (tid & 3) * 16;
            float sv[16];
            const float* srow = Ss + row * AT_LDF + c0;
#pragma unroll
            for (int i = 0; i < 16; i++) sv[i] = srow[i];
            float mx = sv[0];
#pragma unroll
            for (int i = 1; i < 16; i++) mx = fmaxf(mx, sv[i]);
            mx = fmaxf(mx, __shfl_xor_sync(0xffffffffu, mx, 1));
            mx = fmaxf(mx, __shfl_xor_sync(0xffffffffu, mx, 2));
            float m_old = sm_m[row];
            float m_new = fmaxf(m_old, mx);
            float alpha = __expf(m_old - m_new);
            float ssum = 0.0f;
#pragma unroll
            for (int i = 0; i < 16; i++) {
                float p = __expf(sv[i] - m_new);
                sv[i] = p;
                ssum += p;
            }
            ssum += __shfl_xor_sync(0xffffffffu, ssum, 1);
            ssum += __shfl_xor_sync(0xffffffffu, ssum, 2);
            if ((tid & 3) == 0) {
                sm_m[row] = m_new;
                sm_l[row] = sm_l[row] * alpha + ssum;
            }
            __half* ph = p_hi + row * AT_LDH + c0;
            __half* pl = p_lo + row * AT_LDH + c0;
#pragma unroll
            for (int i = 0; i < 16; i++) {
                __half hh = __float2half(sv[i]);
                ph[i] = hh;
                pl[i] = __float2half(sv[i] - __half2float(hh));
            }
            float* orow = Os + row * AT_LDF + c0;
#pragma unroll
            for (int i = 0; i < 16; i++) orow[i] *= alpha;
        }
        __syncthreads();

        {
            wmma::fragment<wmma::accumulator, 16, 16, 16, float> oacc[2];
#pragma unroll
            for (int f = 0; f < 2; f++)
                wmma::load_matrix_sync(oacc[f],
                    Os + wm * 16 * AT_LDF + wn * 32 + f * 16, AT_LDF,
                    wmma::mem_row_major);
#pragma unroll
            for (int kk = 0; kk < 64; kk += 16) {
                wmma::fragment<wmma::matrix_a, 16, 16, 16, __half,
                               wmma::row_major> a_hi, a_lo;
                wmma::load_matrix_sync(a_hi, p_hi + wm * 16 * AT_LDH + kk, AT_LDH);
                wmma::load_matrix_sync(a_lo, p_lo + wm * 16 * AT_LDH + kk, AT_LDH);
#pragma unroll
                for (int f = 0; f < 2; f++) {
                    int j0 = wn * 32 + f * 16;
                    wmma::fragment<wmma::matrix_b, 16, 16, 16, __half,
                                   wmma::row_major> b_hi, b_lo;
                    wmma::load_matrix_sync(b_hi, v_hi + kk * AT_LDH + j0, AT_LDH);
                    wmma::load_matrix_sync(b_lo, v_lo + kk * AT_LDH + j0, AT_LDH);
                    wmma::mma_sync(oacc[f], a_hi, b_hi, oacc[f]);
                    wmma::mma_sync(oacc[f], a_hi, b_lo, oacc[f]);
                    wmma::mma_sync(oacc[f], a_lo, b_hi, oacc[f]);
                }
            }
#pragma unroll
            for (int f = 0; f < 2; f++)
                wmma::store_matrix_sync(
                    Os + wm * 16 * AT_LDF + wn * 32 + f * 16, oacc[f],
                    AT_LDF, wmma::mem_row_major);
        }
        __syncthreads();
    }

    {
        float mk = hm[b * H + h];
        float m2 = mk * mk;
        const int row = tid >> 2;
        const int c0 = (tid & 3) * 16;
        float inv = m2 / sm_l[row];
        float* dst = O + (size_t)(b * N + q0 + row) * C + h * D + c0;
        const float* orow = Os + row * AT_LDF + c0;
#pragma unroll
        for (int i = 0; i < 16; i += 4) {
            float4 o;
            o.x = orow[i + 0] * inv;
            o.y = orow[i + 1] * inv;
            o.z = orow[i + 2] * inv;
            o.w = orow[i + 3] * inv;
            *(float4*)(dst + i) = o;
        }
    }
}

// ---------------- launch ------------------------------------------------------
extern "C" void kernel_launch(void* const* d_in, const int* in_sizes, int n_in,
                              void* d_out, int out_size)
{
    const float* x   = (const float*)d_in[0];
    const float* hm  = (const float*)d_in[1];
    const float* q_w = (const float*)d_in[2];
    const float* q_b = (const float*)d_in[3];
    const float* k_w = (const float*)d_in[4];
    const float* k_b = (const float*)d_in[5];
    const float* v_w = (const float*)d_in[6];
    const float* v_b = (const float*)d_in[7];
    const float* p_w = (const float*)d_in[8];
    const float* p_b = (const float*)d_in[9];
    float* out = (float*)d_out;

    float *pq, *pk, *pv, *pa;
    cudaGetSymbolAddress((void**)&pq, g_q);
    cudaGetSymbolAddress((void**)&pk, g_k);
    cudaGetSymbolAddress((void**)&pv, g_v);
    cudaGetSymbolAddress((void**)&pa, g_att);

    // fused QKV: one launch, z selects weight/bias/dst
    bias_rep3_kernel<<<48, 256>>>(q_b, k_b, v_b);
    dim3 ggrid3(C / 128, M_ROWS / 128, 3);   // (6, 64, 3)
    gemm_wmma<<<ggrid3, 256>>>(x, q_w, k_w, v_w, pq, pk, pv);

    cudaFuncSetAttribute(attn_wmma,
                         cudaFuncAttributeMaxDynamicSharedMemorySize, ATTN_SMEM);
    dim3 attn_grid(N / 64, H, B);            // (16, 12, 8)
    attn_wmma<<<attn_grid, 256, ATTN_SMEM>>>(pq, pk, pv, hm, pa);

    // projection
    bias_rep3_kernel<<<48, 256>>>(p_b, nullptr, nullptr);
    dim3 ggrid1(C / 128, M_ROWS / 128, 1);
    gemm_wmma<<<ggrid1, 256>>>(pa, p_w, p_w, p_w, out, out, out);
}